// round 1
// baseline (speedup 1.0000x reference)
#include <cuda_runtime.h>

#define BTOT   500000
#define NDIM   3
#define NCOND  64
#define NHID   128
#define NIN    68      // NDIM + NCOND + 1
#define TILE   64
#define NTHREADS 256

// Scratch for transposed hidden-layer weights (backward pass).
__device__ float g_Wt1[NHID * NHID];
__device__ float g_Wt2[NHID * NHID];

__global__ void transpose_k(const float* __restrict__ W1, const float* __restrict__ W2) {
    int idx = blockIdx.x * blockDim.x + threadIdx.x;
    if (idx < NHID * NHID) {
        int r = idx >> 7;      // row in W (input unit)
        int c = idx & 127;     // col in W (output unit)
        g_Wt1[c * NHID + r] = W1[idx];
        g_Wt2[c * NHID + r] = W2[idx];
    }
}

__device__ __forceinline__ float ftanh(float x) {
    float e = __expf(2.0f * x);
    return __fdividef(e - 1.0f, e + 1.0f);
}

// out[r0..r0+3][j0..j0+7] accumulation: acc[u][c] = sum_k sA[k][r0+u] * sW[k][j0+c]
// sA layout: [K][TILE] (activation transposed), sW layout: [K][NHID] row-major.
__device__ __forceinline__ void mm_core(const float* __restrict__ sA,
                                        const float* __restrict__ sW,
                                        int K, int r0, int j0,
                                        float acc[4][8]) {
#pragma unroll
    for (int u = 0; u < 4; u++)
#pragma unroll
        for (int c = 0; c < 8; c++) acc[u][c] = 0.0f;

#pragma unroll 4
    for (int k = 0; k < K; k++) {
        float4 a  = *(const float4*)(sA + k * TILE + r0);
        float4 w0 = *(const float4*)(sW + k * NHID + j0);
        float4 w1 = *(const float4*)(sW + k * NHID + j0 + 4);
        float av[4] = {a.x, a.y, a.z, a.w};
        float wv[8] = {w0.x, w0.y, w0.z, w0.w, w1.x, w1.y, w1.z, w1.w};
#pragma unroll
        for (int u = 0; u < 4; u++)
#pragma unroll
            for (int c = 0; c < 8; c++)
                acc[u][c] = fmaf(av[u], wv[c], acc[u][c]);
    }
}

__global__ __launch_bounds__(NTHREADS, 1)
void ode_kernel(const float* __restrict__ t_p,
                const float* __restrict__ z,
                const float* __restrict__ context,
                const float* __restrict__ eps,
                const float* __restrict__ W_in,  const float* __restrict__ b_in,
                const float* __restrict__ W_h1,  const float* __restrict__ b_h1,
                const float* __restrict__ W_h2,  const float* __restrict__ b_h2,
                const float* __restrict__ W_out, const float* __restrict__ b_out,
                const float* __restrict__ scale_p,
                float* __restrict__ out)
{
    extern __shared__ float sm[];
    float* sIn = sm;                         // NIN  * TILE = 4352
    float* sH1 = sIn + NIN * TILE;           // NHID * TILE = 8192
    float* sH2 = sH1 + NHID * TILE;
    float* sH3 = sH2 + NHID * TILE;
    float* sG  = sH3 + NHID * TILE;
    float* sW  = sG  + NHID * TILE;          // NHID * NHID = 16384
    float* sB  = sW  + NHID * NHID;          // NHID

    const int t    = threadIdx.x;
    const int row0 = blockIdx.x * TILE;
    const int cg = t & 15;          // 16 col groups * 8 cols
    const int rg = t >> 4;          // 16 row groups * 4 rows
    const int j0 = cg * 8;
    const int r0 = rg * 4;
    const float tval   = *t_p;
    const float oscale = *scale_p;

    // ---- Load input tile transposed: sIn[k][r], plus W_in, b_in ----
    for (int idx = t; idx < NIN * TILE; idx += NTHREADS) {
        int k = idx >> 6;
        int r = idx & 63;
        int grow = row0 + r;
        float v = 0.0f;
        if (grow < BTOT) {
            if (k < NDIM)              v = z[grow * NDIM + k];
            else if (k < NDIM + NCOND) v = context[grow * NCOND + (k - NDIM)];
            else                       v = tval;
        }
        sIn[idx] = v;
    }
    for (int idx = t; idx < NIN * NHID; idx += NTHREADS) sW[idx] = W_in[idx];
    if (t < NHID) sB[t] = b_in[t];
    __syncthreads();

    float acc[4][8];

    // ---- Layer 1: h1 = tanh(inp @ W_in + b_in) ----
    mm_core(sIn, sW, NIN, r0, j0, acc);
#pragma unroll
    for (int c = 0; c < 8; c++) {
        float b = sB[j0 + c];
        float4 v;
        v.x = ftanh(acc[0][c] + b);
        v.y = ftanh(acc[1][c] + b);
        v.z = ftanh(acc[2][c] + b);
        v.w = ftanh(acc[3][c] + b);
        *(float4*)(sH1 + (j0 + c) * TILE + r0) = v;
    }
    __syncthreads();

    // ---- Layer 2 ----
    for (int idx = t; idx < NHID * NHID; idx += NTHREADS) sW[idx] = W_h1[idx];
    if (t < NHID) sB[t] = b_h1[t];
    __syncthreads();
    mm_core(sH1, sW, NHID, r0, j0, acc);
#pragma unroll
    for (int c = 0; c < 8; c++) {
        float b = sB[j0 + c];
        float4 v;
        v.x = ftanh(acc[0][c] + b);
        v.y = ftanh(acc[1][c] + b);
        v.z = ftanh(acc[2][c] + b);
        v.w = ftanh(acc[3][c] + b);
        *(float4*)(sH2 + (j0 + c) * TILE + r0) = v;
    }
    __syncthreads();

    // ---- Layer 3 ----
    for (int idx = t; idx < NHID * NHID; idx += NTHREADS) sW[idx] = W_h2[idx];
    if (t < NHID) sB[t] = b_h2[t];
    __syncthreads();
    mm_core(sH2, sW, NHID, r0, j0, acc);
#pragma unroll
    for (int c = 0; c < 8; c++) {
        float b = sB[j0 + c];
        float4 v;
        v.x = ftanh(acc[0][c] + b);
        v.y = ftanh(acc[1][c] + b);
        v.z = ftanh(acc[2][c] + b);
        v.w = ftanh(acc[3][c] + b);
        *(float4*)(sH3 + (j0 + c) * TILE + r0) = v;
    }
    __syncthreads();

    // ---- Output f = (h3 @ W_out + b_out) * out_scale ; load eps tile ----
    float* sEps = sIn;   // sIn is dead now; reuse for eps tile [r][d]
    if (t < TILE * NDIM) {
        int gi = row0 * NDIM + t;
        sEps[t] = (gi < BTOT * NDIM) ? eps[gi] : 0.0f;
    }
    if (t < TILE * NDIM) {            // 192 threads: one (row, d) each
        int r = t / 3, d = t - r * 3;
        int grow = row0 + r;
        float s = b_out[d];
#pragma unroll 4
        for (int j = 0; j < NHID; j++)
            s = fmaf(sH3[j * TILE + r], W_out[j * NDIM + d], s);
        if (grow < BTOT) out[grow * NDIM + d] = s * oscale;
    }
    __syncthreads();

    // ---- g3 = (out_scale * eps @ W_out^T) * (1 - h3^2) ----
    for (int idx = t; idx < NHID * TILE; idx += NTHREADS) {
        int j = idx >> 6;
        int r = idx & 63;
        float s = sEps[r * 3 + 0] * W_out[j * 3 + 0]
                + sEps[r * 3 + 1] * W_out[j * 3 + 1]
                + sEps[r * 3 + 2] * W_out[j * 3 + 2];
        float h = sH3[idx];
        sG[idx] = s * oscale * (1.0f - h * h);
    }
    __syncthreads();

    // ---- g2 = (g3 @ W_h2^T) * (1 - h2^2)  -> stored into sH3 (h3 dead) ----
    for (int idx = t; idx < NHID * NHID; idx += NTHREADS) sW[idx] = g_Wt2[idx];
    __syncthreads();
    mm_core(sG, sW, NHID, r0, j0, acc);
#pragma unroll
    for (int c = 0; c < 8; c++) {
        float4 h = *(const float4*)(sH2 + (j0 + c) * TILE + r0);
        float4 v;
        v.x = acc[0][c] * (1.0f - h.x * h.x);
        v.y = acc[1][c] * (1.0f - h.y * h.y);
        v.z = acc[2][c] * (1.0f - h.z * h.z);
        v.w = acc[3][c] * (1.0f - h.w * h.w);
        *(float4*)(sH3 + (j0 + c) * TILE + r0) = v;
    }
    __syncthreads();

    // ---- g1 = (g2 @ W_h1^T) * (1 - h1^2)  -> stored into sG (g3 dead) ----
    for (int idx = t; idx < NHID * NHID; idx += NTHREADS) sW[idx] = g_Wt1[idx];
    __syncthreads();
    mm_core(sH3, sW, NHID, r0, j0, acc);
#pragma unroll
    for (int c = 0; c < 8; c++) {
        float4 h = *(const float4*)(sH1 + (j0 + c) * TILE + r0);
        float4 v;
        v.x = acc[0][c] * (1.0f - h.x * h.x);
        v.y = acc[1][c] * (1.0f - h.y * h.y);
        v.z = acc[2][c] * (1.0f - h.z * h.z);
        v.w = acc[3][c] * (1.0f - h.w * h.w);
        *(float4*)(sG + (j0 + c) * TILE + r0) = v;
    }
    __syncthreads();

    // ---- gz[d] = sum_j g1[j] * W_in[d][j] ; neg_div = -(gz . eps) ----
    if (t < TILE) {
        int r = t;
        int grow = row0 + r;
        float g0 = 0.0f, g1v = 0.0f, g2v = 0.0f;
#pragma unroll 4
        for (int j = 0; j < NHID; j++) {
            float g = sG[j * TILE + r];
            g0  = fmaf(g, W_in[0 * NHID + j], g0);
            g1v = fmaf(g, W_in[1 * NHID + j], g1v);
            g2v = fmaf(g, W_in[2 * NHID + j], g2v);
        }
        float nd = -(g0 * sEps[r * 3 + 0] + g1v * sEps[r * 3 + 1] + g2v * sEps[r * 3 + 2]);
        if (grow < BTOT) out[BTOT * NDIM + grow] = nd;
    }
}

extern "C" void kernel_launch(void* const* d_in, const int* in_sizes, int n_in,
                              void* d_out, int out_size) {
    const float* t_p     = (const float*)d_in[0];
    const float* z       = (const float*)d_in[1];
    // d_in[2] = logp (unused)
    const float* context = (const float*)d_in[3];
    const float* eps     = (const float*)d_in[4];
    const float* W_in    = (const float*)d_in[5];
    const float* b_in    = (const float*)d_in[6];
    const float* W_h1    = (const float*)d_in[7];
    const float* b_h1    = (const float*)d_in[8];
    const float* W_h2    = (const float*)d_in[9];
    const float* b_h2    = (const float*)d_in[10];
    const float* W_out   = (const float*)d_in[11];
    const float* b_out   = (const float*)d_in[12];
    const float* scale_p = (const float*)d_in[13];
    float* out = (float*)d_out;

    const int smem_bytes = (NIN * TILE + 4 * NHID * TILE + NHID * NHID + NHID) * (int)sizeof(float);
    cudaFuncSetAttribute(ode_kernel, cudaFuncAttributeMaxDynamicSharedMemorySize, smem_bytes);

    transpose_k<<<(NHID * NHID + 255) / 256, 256>>>(W_h1, W_h2);

    const int grid = (BTOT + TILE - 1) / TILE;   // 7813
    ode_kernel<<<grid, NTHREADS, smem_bytes>>>(t_p, z, context, eps,
                                               W_in, b_in, W_h1, b_h1, W_h2, b_h2,
                                               W_out, b_out, scale_p, out);
}

// round 5
// speedup vs baseline: 1.6969x; 1.6969x over previous
#include <cuda_runtime.h>
#include <cstdint>

#define BTOT   500000
#define NDIM   3
#define NCOND  64
#define NHID   128
#define NIN    68      // NDIM + NCOND + 1
#define TILE   64
#define NT     256

typedef unsigned long long ull;

// Transposed hidden-layer weights for backward pass.
__device__ float g_Wt1[NHID * NHID];
__device__ float g_Wt2[NHID * NHID];

__global__ void transpose_k(const float* __restrict__ W1, const float* __restrict__ W2) {
    int idx = blockIdx.x * blockDim.x + threadIdx.x;
    if (idx < NHID * NHID) {
        int r = idx >> 7, c = idx & 127;
        g_Wt1[c * NHID + r] = W1[idx];
        g_Wt2[c * NHID + r] = W2[idx];
    }
}

__device__ __forceinline__ float ftanh(float x) {
    float e = __expf(2.0f * x);
    return __fdividef(e - 1.0f, e + 1.0f);
}

__device__ __forceinline__ ull pk(float lo, float hi) {
    ull r; asm("mov.b64 %0, {%1,%2};" : "=l"(r) : "f"(lo), "f"(hi)); return r;
}
__device__ __forceinline__ void upk(ull v, float& lo, float& hi) {
    asm("mov.b64 {%0,%1}, %2;" : "=f"(lo), "=f"(hi) : "l"(v));
}
__device__ __forceinline__ void fma2(ull& d, ull a, ull b) {
    asm("fma.rn.f32x2 %0, %1, %2, %3;" : "=l"(d) : "l"(a), "l"(b), "l"(d));
}

// acc[u][cp]: rows (r2+u), col-pair (j0+2cp, j0+2cp+1).
// sA: [K][TILE] transposed activations. sW: [K][NHID] row-major.
// Within a warp: A load = conflict-free float2, W loads = broadcast LDS.128.
template<int K>
__device__ __forceinline__ void mmf2(const float* __restrict__ sA,
                                     const float* __restrict__ sW,
                                     int r2, int j0, ull acc[2][8]) {
#pragma unroll
    for (int u = 0; u < 2; u++)
#pragma unroll
        for (int c = 0; c < 8; c++) acc[u][c] = 0ULL;

#pragma unroll 4
    for (int k = 0; k < K; k++) {
        float2 a = *reinterpret_cast<const float2*>(sA + k * TILE + r2);
        ull a0 = pk(a.x, a.x);
        ull a1 = pk(a.y, a.y);
        const ulonglong2* wp = reinterpret_cast<const ulonglong2*>(sW + k * NHID + j0);
        ulonglong2 q0 = wp[0], q1 = wp[1], q2 = wp[2], q3 = wp[3];
        ull w[8] = {q0.x, q0.y, q1.x, q1.y, q2.x, q2.y, q3.x, q3.y};
#pragma unroll
        for (int c = 0; c < 8; c++) { fma2(acc[0][c], a0, w[c]); fma2(acc[1][c], a1, w[c]); }
    }
}

__device__ __forceinline__ void epi_tanh(ull acc[2][8], const float* __restrict__ bias,
                                         float* __restrict__ sH, int r2, int j0) {
#pragma unroll
    for (int c = 0; c < 8; c++) {
        int j = j0 + 2 * c;
        float b0 = __ldg(bias + j), b1 = __ldg(bias + j + 1);
        float x00, x01, x10, x11;
        upk(acc[0][c], x00, x01);   // row r2:   cols j, j+1
        upk(acc[1][c], x10, x11);   // row r2+1: cols j, j+1
        *reinterpret_cast<float2*>(sH + j * TILE + r2) =
            make_float2(ftanh(x00 + b0), ftanh(x10 + b0));
        *reinterpret_cast<float2*>(sH + (j + 1) * TILE + r2) =
            make_float2(ftanh(x01 + b1), ftanh(x11 + b1));
    }
}

// dst = acc * (1 - h^2), h read from sHprev at same slots; dst may alias sHprev.
__device__ __forceinline__ void epi_bwd(ull acc[2][8], const float* __restrict__ sHprev,
                                        float* __restrict__ sDst, int r2, int j0) {
#pragma unroll
    for (int c = 0; c < 8; c++) {
        int j = j0 + 2 * c;
        float x00, x01, x10, x11;
        upk(acc[0][c], x00, x01);
        upk(acc[1][c], x10, x11);
        float2 h0 = *reinterpret_cast<const float2*>(sHprev + j * TILE + r2);
        float2 h1 = *reinterpret_cast<const float2*>(sHprev + (j + 1) * TILE + r2);
        *reinterpret_cast<float2*>(sDst + j * TILE + r2) =
            make_float2(x00 * (1.0f - h0.x * h0.x), x10 * (1.0f - h0.y * h0.y));
        *reinterpret_cast<float2*>(sDst + (j + 1) * TILE + r2) =
            make_float2(x01 * (1.0f - h1.x * h1.x), x11 * (1.0f - h1.y * h1.y));
    }
}

__device__ __forceinline__ void stage_cp(float* smDst, const float* g, int n4, int t) {
    unsigned int s = (unsigned int)__cvta_generic_to_shared(smDst);
    for (int i = t; i < n4; i += NT)
        asm volatile("cp.async.cg.shared.global [%0], [%1], 16;"
                     :: "r"(s + i * 16), "l"(g + i * 4));
}
#define CPA_COMMIT()  asm volatile("cp.async.commit_group;")
#define CPA_WAIT(n)   asm volatile("cp.async.wait_group %0;" :: "n"(n))

__global__ __launch_bounds__(NT, 1)
void ode_kernel(const float* __restrict__ t_p,
                const float* __restrict__ z,
                const float* __restrict__ context,
                const float* __restrict__ eps,
                const float* __restrict__ W_in,  const float* __restrict__ b_in,
                const float* __restrict__ W_h1,  const float* __restrict__ b_h1,
                const float* __restrict__ W_h2,  const float* __restrict__ b_h2,
                const float* __restrict__ W_out, const float* __restrict__ b_out,
                const float* __restrict__ scale_p,
                float* __restrict__ out)
{
    extern __shared__ float sm[];
    float* sW0  = sm;                 // 16384 floats (64KB) — W_in (8704) + sIn (4352 at tail)
    float* sW1  = sm + 16384;         // 16384 floats
    float* sH1  = sm + 32768;         // 8192
    float* sH2  = sm + 40960;         // 8192
    float* sH3  = sm + 49152;         // 8192
    float* sEps = sm + 57344;         // 192
    float* sIn  = sW0 + 8704;         // 68*64 = 4352 floats

    const int t    = threadIdx.x;
    const int lane = t & 31;
    const int warp = t >> 5;
    const int j0   = warp * 16;
    const int r2   = lane * 2;
    const int row0 = blockIdx.x * TILE;
    const float tval   = *t_p;
    const float oscale = *scale_p;

    // G0: W_in -> sW0 ; G1: W_h1 -> sW1 (prefetch)
    stage_cp(sW0, W_in, (NIN * NHID) / 4, t); CPA_COMMIT();
    stage_cp(sW1, W_h1, (NHID * NHID) / 4, t); CPA_COMMIT();

    // Input tile transposed sIn[k][r] + eps tile (regular stores).
    for (int idx = t; idx < NIN * TILE; idx += NT) {
        int k = idx >> 6, r = idx & 63;
        int grow = row0 + r;
        float v = 0.0f;
        if (grow < BTOT) {
            if (k < NDIM)              v = z[grow * NDIM + k];
            else if (k < NDIM + NCOND) v = context[grow * NCOND + (k - NDIM)];
            else                       v = tval;
        }
        sIn[idx] = v;
    }
    if (t < TILE * NDIM) {
        int gi = row0 * NDIM + t;
        sEps[t] = (gi < BTOT * NDIM) ? eps[gi] : 0.0f;
    }
    CPA_WAIT(1); __syncthreads();          // W_in + sIn + eps ready (W_h1 in flight)

    ull acc[2][8];

    // ---- L1: h1 = tanh(inp @ W_in + b_in) ----
    mmf2<NIN>(sIn, sW0, r2, j0, acc);
    epi_tanh(acc, b_in, sH1, r2, j0);
    __syncthreads();

    stage_cp(sW0, W_h2, (NHID * NHID) / 4, t); CPA_COMMIT();   // G2
    CPA_WAIT(1); __syncthreads();          // W_h1 ready

    // ---- L2 ----
    mmf2<NHID>(sH1, sW1, r2, j0, acc);
    epi_tanh(acc, b_h1, sH2, r2, j0);
    __syncthreads();

    stage_cp(sW1, g_Wt2, (NHID * NHID) / 4, t); CPA_COMMIT();  // G3
    CPA_WAIT(1); __syncthreads();          // W_h2 ready

    // ---- L3 ----
    mmf2<NHID>(sH2, sW0, r2, j0, acc);
    epi_tanh(acc, b_h2, sH3, r2, j0);
    __syncthreads();

    stage_cp(sW0, g_Wt1, (NHID * NHID) / 4, t); CPA_COMMIT();  // G4

    // ---- out: f = (h3 @ W_out + b_out) * out_scale ----
    if (t < TILE * NDIM) {
        int r = t / 3, d = t - r * 3;
        int grow = row0 + r;
        float s = __ldg(b_out + d);
#pragma unroll 4
        for (int j = 0; j < NHID; j++)
            s = fmaf(sH3[j * TILE + r], __ldg(W_out + j * NDIM + d), s);
        if (grow < BTOT) out[grow * NDIM + d] = s * oscale;
    }
    __syncthreads();   // all reads of h3 done before overwrite

    // ---- g3 = (out_scale * eps @ W_out^T) * (1 - h3^2), overwrite sH3 ----
    for (int idx = t; idx < NHID * TILE; idx += NT) {
        int j = idx >> 6, r = idx & 63;
        float s = sEps[r * 3 + 0] * __ldg(W_out + j * 3 + 0)
                + sEps[r * 3 + 1] * __ldg(W_out + j * 3 + 1)
                + sEps[r * 3 + 2] * __ldg(W_out + j * 3 + 2);
        float h = sH3[idx];
        sH3[idx] = s * oscale * (1.0f - h * h);
    }
    __syncthreads();

    CPA_WAIT(1); __syncthreads();          // Wt2 ready

    // ---- g2 = (g3 @ Wt2) * (1 - h2^2), overwrite sH2 ----
    mmf2<NHID>(sH3, sW1, r2, j0, acc);
    epi_bwd(acc, sH2, sH2, r2, j0);
    __syncthreads();

    CPA_WAIT(0); __syncthreads();          // Wt1 ready

    // ---- g1 = (g2 @ Wt1) * (1 - h1^2), overwrite sH1 ----
    mmf2<NHID>(sH2, sW0, r2, j0, acc);
    epi_bwd(acc, sH1, sH1, r2, j0);
    __syncthreads();

    // ---- gz[d] = sum_j g1[j] * W_in[d][j]; neg_div = -(gz . eps) ----
    if (t < TILE) {
        int r = t, grow = row0 + r;
        float g0 = 0.0f, g1v = 0.0f, g2v = 0.0f;
#pragma unroll 4
        for (int j = 0; j < NHID; j++) {
            float g = sH1[j * TILE + r];
            g0  = fmaf(g, __ldg(W_in + 0 * NHID + j), g0);
            g1v = fmaf(g, __ldg(W_in + 1 * NHID + j), g1v);
            g2v = fmaf(g, __ldg(W_in + 2 * NHID + j), g2v);
        }
        float nd = -(g0 * sEps[r * 3 + 0] + g1v * sEps[r * 3 + 1] + g2v * sEps[r * 3 + 2]);
        if (grow < BTOT) out[BTOT * NDIM + grow] = nd;
    }
}

extern "C" void kernel_launch(void* const* d_in, const int* in_sizes, int n_in,
                              void* d_out, int out_size) {
    const float* t_p     = (const float*)d_in[0];
    const float* z       = (const float*)d_in[1];
    const float* context = (const float*)d_in[3];
    const float* eps     = (const float*)d_in[4];
    const float* W_in    = (const float*)d_in[5];
    const float* b_in    = (const float*)d_in[6];
    const float* W_h1    = (const float*)d_in[7];
    const float* b_h1    = (const float*)d_in[8];
    const float* W_h2    = (const float*)d_in[9];
    const float* b_h2    = (const float*)d_in[10];
    const float* W_out   = (const float*)d_in[11];
    const float* b_out   = (const float*)d_in[12];
    const float* scale_p = (const float*)d_in[13];
    float* out = (float*)d_out;

    const int smem_bytes = (2 * NHID * NHID + 3 * NHID * TILE + 192) * (int)sizeof(float); // 230,144 B
    cudaFuncSetAttribute(ode_kernel, cudaFuncAttributeMaxDynamicSharedMemorySize, smem_bytes);

    transpose_k<<<(NHID * NHID + 255) / 256, 256>>>(W_h1, W_h2);

    const int grid = (BTOT + TILE - 1) / TILE;   // 7813
    ode_kernel<<<grid, NT, smem_bytes>>>(t_p, z, context, eps,
                                         W_in, b_in, W_h1, b_h1, W_h2, b_h2,
                                         W_out, b_out, scale_p, out);
}